// round 2
// baseline (speedup 1.0000x reference)
#include <cuda_runtime.h>
#include <cuda_bf16.h>
#include <cstddef>

// Problem constants
#define D_MODEL   1024
#define NUM_HEADS 16
#define N_GROUP   4
#define HEAD_DIM  64
#define KV_DIM    (N_GROUP * HEAD_DIM)   // 256
#define BS        2
#define SEQ       2048
#define ROWS      (BS * SEQ)             // 4096

// Scratch buffers (device globals: no allocation allowed in kernel_launch)
__device__ float g_q[ROWS * D_MODEL];   // 16 MB
__device__ float g_k[ROWS * KV_DIM];    //  4 MB
__device__ float g_v[ROWS * KV_DIM];    //  4 MB

// ---------------------------------------------------------------------------
// GEMM: C[m][n] = sum_k A[m][k] * B[n][k] + bias[n]
// A: [M,K] row-major, B: [N,K] row-major (i.e. x @ W^T + b, torch Linear)
// 64x64 tile, 256 threads, 4x4 per thread, k-step 16.
// ---------------------------------------------------------------------------
__global__ __launch_bounds__(256)
void gemm_nt_bias(const float* __restrict__ A, const float* __restrict__ B,
                  const float* __restrict__ bias, float* __restrict__ C,
                  int M, int N, int K)
{
    __shared__ float As[16 * 64];
    __shared__ float Bs[16 * 64];

    const int tid = threadIdx.x;          // 0..255
    const int tx  = tid & 15;             // 0..15
    const int ty  = tid >> 4;             // 0..15
    const int m0  = blockIdx.y * 64;
    const int n0  = blockIdx.x * 64;

    const int lr = tid >> 2;              // 0..63 (row within tile for loading)
    const int lk = tid & 3;               // 0..3  (float4 index along k)

    float acc[4][4];
#pragma unroll
    for (int i = 0; i < 4; i++)
#pragma unroll
        for (int j = 0; j < 4; j++) acc[i][j] = 0.f;

    for (int k0 = 0; k0 < K; k0 += 16) {
        // Load A tile (64 x 16) and B tile (64 x 16), transposed into [kk][row]
        float4 a = *(const float4*)(A + (size_t)(m0 + lr) * K + k0 + lk * 4);
        float4 bvec = *(const float4*)(B + (size_t)(n0 + lr) * K + k0 + lk * 4);
        As[(lk * 4 + 0) * 64 + lr] = a.x;
        As[(lk * 4 + 1) * 64 + lr] = a.y;
        As[(lk * 4 + 2) * 64 + lr] = a.z;
        As[(lk * 4 + 3) * 64 + lr] = a.w;
        Bs[(lk * 4 + 0) * 64 + lr] = bvec.x;
        Bs[(lk * 4 + 1) * 64 + lr] = bvec.y;
        Bs[(lk * 4 + 2) * 64 + lr] = bvec.z;
        Bs[(lk * 4 + 3) * 64 + lr] = bvec.w;
        __syncthreads();

#pragma unroll
        for (int kk = 0; kk < 16; kk++) {
            float4 av = *(const float4*)(As + kk * 64 + ty * 4);
            float4 bv = *(const float4*)(Bs + kk * 64 + tx * 4);
            float ar[4] = {av.x, av.y, av.z, av.w};
            float br[4] = {bv.x, bv.y, bv.z, bv.w};
#pragma unroll
            for (int i = 0; i < 4; i++)
#pragma unroll
                for (int j = 0; j < 4; j++)
                    acc[i][j] = fmaf(ar[i], br[j], acc[i][j]);
        }
        __syncthreads();
    }

#pragma unroll
    for (int i = 0; i < 4; i++) {
        const int m = m0 + ty * 4 + i;
        float* crow = C + (size_t)m * N + n0 + tx * 4;
        float4 out;
        out.x = acc[i][0] + bias[n0 + tx * 4 + 0];
        out.y = acc[i][1] + bias[n0 + tx * 4 + 1];
        out.z = acc[i][2] + bias[n0 + tx * 4 + 2];
        out.w = acc[i][3] + bias[n0 + tx * 4 + 3];
        *(float4*)crow = out;
    }
}

// ---------------------------------------------------------------------------
// Flash attention (non-causal, GQA).
// Grid: (SEQ/BQ, NUM_HEADS, BS). Block: BQ=128 threads, one thread per q row.
// K/V tiles (BK=64 x 64) staged in smem; scores scratch P in padded smem.
// Q row and O accumulator live in registers (16 float4 each).
// ---------------------------------------------------------------------------
#define BQ 128
#define BK 64

__global__ __launch_bounds__(BQ)
void attn_kernel(const float* __restrict__ Q, const float* __restrict__ Kb,
                 const float* __restrict__ Vb, float* __restrict__ O)
{
    extern __shared__ float sm[];
    float* Ks = sm;                    // 64*64 floats
    float* Vs = sm + 64 * 64;          // 64*64 floats
    float* Ps = sm + 2 * 64 * 64;      // BQ * 65 floats (padded)

    const int t  = threadIdx.x;        // q row within tile
    const int h  = blockIdx.y;
    const int b  = blockIdx.z;
    const int g  = h >> 2;             // kv group = h / (NUM_HEADS/N_GROUP)
    const int sq = blockIdx.x * BQ + t;

    // Load q row, pre-scaled by 1/sqrt(d)
    float4 q4[16];
    {
        const float4* qp = (const float4*)(Q + ((size_t)(b * SEQ + sq)) * D_MODEL + h * HEAD_DIM);
        const float scale = 0.125f;    // 1/sqrt(64)
#pragma unroll
        for (int i = 0; i < 16; i++) {
            float4 v = qp[i];
            q4[i] = make_float4(v.x * scale, v.y * scale, v.z * scale, v.w * scale);
        }
    }

    float4 o4[16];
#pragma unroll
    for (int i = 0; i < 16; i++) o4[i] = make_float4(0.f, 0.f, 0.f, 0.f);
    float m = -1e30f, l = 0.f;

    float* myP = Ps + t * 65;

    for (int kt = 0; kt < SEQ / BK; kt++) {
        __syncthreads();   // previous tile's compute finished before overwrite
        // Cooperative load of K and V tiles: 64 rows x 64 floats each
        {
            const float* kbase = Kb + ((size_t)(b * SEQ + kt * BK)) * KV_DIM + g * HEAD_DIM;
            const float* vbase = Vb + ((size_t)(b * SEQ + kt * BK)) * KV_DIM + g * HEAD_DIM;
#pragma unroll
            for (int i = t; i < 64 * 16; i += BQ) {
                int r = i >> 4, c = i & 15;
                ((float4*)Ks)[i] = *(const float4*)(kbase + (size_t)r * KV_DIM + c * 4);
                ((float4*)Vs)[i] = *(const float4*)(vbase + (size_t)r * KV_DIM + c * 4);
            }
        }
        __syncthreads();

        // S = q . K_j  for 64 keys, 4 at a time (register-blocked)
        float mt = m;
        for (int j0 = 0; j0 < BK; j0 += 4) {
            float a0 = 0.f, a1 = 0.f, a2 = 0.f, a3 = 0.f;
            const float4* k0 = (const float4*)(Ks + (j0 + 0) * 64);
            const float4* k1 = (const float4*)(Ks + (j0 + 1) * 64);
            const float4* k2 = (const float4*)(Ks + (j0 + 2) * 64);
            const float4* k3 = (const float4*)(Ks + (j0 + 3) * 64);
#pragma unroll
            for (int d = 0; d < 16; d++) {
                float4 qq = q4[d];
                float4 w0 = k0[d], w1 = k1[d], w2 = k2[d], w3 = k3[d];
                a0 = fmaf(qq.x, w0.x, a0); a0 = fmaf(qq.y, w0.y, a0);
                a0 = fmaf(qq.z, w0.z, a0); a0 = fmaf(qq.w, w0.w, a0);
                a1 = fmaf(qq.x, w1.x, a1); a1 = fmaf(qq.y, w1.y, a1);
                a1 = fmaf(qq.z, w1.z, a1); a1 = fmaf(qq.w, w1.w, a1);
                a2 = fmaf(qq.x, w2.x, a2); a2 = fmaf(qq.y, w2.y, a2);
                a2 = fmaf(qq.z, w2.z, a2); a2 = fmaf(qq.w, w2.w, a2);
                a3 = fmaf(qq.x, w3.x, a3); a3 = fmaf(qq.y, w3.y, a3);
                a3 = fmaf(qq.z, w3.z, a3); a3 = fmaf(qq.w, w3.w, a3);
            }
            myP[j0 + 0] = a0;
            myP[j0 + 1] = a1;
            myP[j0 + 2] = a2;
            myP[j0 + 3] = a3;
            mt = fmaxf(mt, fmaxf(fmaxf(a0, a1), fmaxf(a2, a3)));
        }

        // Online softmax rescale
        float corr = __expf(m - mt);
        l *= corr;
#pragma unroll
        for (int i = 0; i < 16; i++) {
            o4[i].x *= corr; o4[i].y *= corr; o4[i].z *= corr; o4[i].w *= corr;
        }

        // O += P @ V
        for (int j = 0; j < BK; j++) {
            float p = __expf(myP[j] - mt);
            l += p;
            const float4* vv = (const float4*)(Vs + j * 64);
#pragma unroll
            for (int i = 0; i < 16; i++) {
                float4 w = vv[i];
                o4[i].x = fmaf(p, w.x, o4[i].x);
                o4[i].y = fmaf(p, w.y, o4[i].y);
                o4[i].z = fmaf(p, w.z, o4[i].z);
                o4[i].w = fmaf(p, w.w, o4[i].w);
            }
        }
        m = mt;
    }

    const float inv = 1.f / l;
    float4* op = (float4*)(O + ((size_t)(b * SEQ + sq)) * D_MODEL + h * HEAD_DIM);
#pragma unroll
    for (int i = 0; i < 16; i++) {
        op[i] = make_float4(o4[i].x * inv, o4[i].y * inv, o4[i].z * inv, o4[i].w * inv);
    }
}

// ---------------------------------------------------------------------------
// Launch
// ---------------------------------------------------------------------------
extern "C" void kernel_launch(void* const* d_in, const int* in_sizes, int n_in,
                              void* d_out, int out_size)
{
    const float* h    = (const float*)d_in[0];
    const float* wq_w = (const float*)d_in[1];
    const float* wq_b = (const float*)d_in[2];
    const float* wk_w = (const float*)d_in[3];
    const float* wk_b = (const float*)d_in[4];
    const float* wv_w = (const float*)d_in[5];
    const float* wv_b = (const float*)d_in[6];
    float* out = (float*)d_out;

    float* qb; cudaGetSymbolAddress((void**)&qb, g_q);
    float* kb; cudaGetSymbolAddress((void**)&kb, g_k);
    float* vb; cudaGetSymbolAddress((void**)&vb, g_v);

    // QKV projections
    {
        dim3 blk(256);
        dim3 gq(D_MODEL / 64, ROWS / 64);
        gemm_nt_bias<<<gq, blk>>>(h, wq_w, wq_b, qb, ROWS, D_MODEL, D_MODEL);
        dim3 gk(KV_DIM / 64, ROWS / 64);
        gemm_nt_bias<<<gk, blk>>>(h, wk_w, wk_b, kb, ROWS, KV_DIM, D_MODEL);
        gemm_nt_bias<<<gk, blk>>>(h, wv_w, wv_b, vb, ROWS, KV_DIM, D_MODEL);
    }

    // Flash attention
    {
        const size_t smem = (size_t)(2 * 64 * 64 + BQ * 65) * sizeof(float); // 66048 B
        cudaFuncSetAttribute(attn_kernel, cudaFuncAttributeMaxDynamicSharedMemorySize, (int)smem);
        dim3 grid(SEQ / BQ, NUM_HEADS, BS);
        attn_kernel<<<grid, BQ, smem>>>(qb, kb, vb, out);
    }
}

// round 3
// speedup vs baseline: 1.0007x; 1.0007x over previous
#include <cuda_runtime.h>
#include <cuda_bf16.h>
#include <cstddef>

// Problem constants
#define D_MODEL   1024
#define NUM_HEADS 16
#define N_GROUP   4
#define HEAD_DIM  64
#define KV_DIM    (N_GROUP * HEAD_DIM)   // 256
#define BS        2
#define SEQ       2048
#define ROWS      (BS * SEQ)             // 4096

// Scratch buffers (device globals: no allocation allowed in kernel_launch)
__device__ float g_q[ROWS * D_MODEL];   // 16 MB
__device__ float g_k[ROWS * KV_DIM];    //  4 MB
__device__ float g_v[ROWS * KV_DIM];    //  4 MB

// ---------------------------------------------------------------------------
// GEMM: C[m][n] = sum_k A[m][k] * B[n][k] + bias[n]
// A: [M,K] row-major, B: [N,K] row-major (i.e. x @ W^T + b, torch Linear)
// 64x64 tile, 256 threads, 4x4 per thread, k-step 16.
// ---------------------------------------------------------------------------
__global__ __launch_bounds__(256)
void gemm_nt_bias(const float* __restrict__ A, const float* __restrict__ B,
                  const float* __restrict__ bias, float* __restrict__ C,
                  int M, int N, int K)
{
    __shared__ float As[16 * 64];
    __shared__ float Bs[16 * 64];

    const int tid = threadIdx.x;          // 0..255
    const int tx  = tid & 15;             // 0..15
    const int ty  = tid >> 4;             // 0..15
    const int m0  = blockIdx.y * 64;
    const int n0  = blockIdx.x * 64;

    const int lr = tid >> 2;              // 0..63 (row within tile for loading)
    const int lk = tid & 3;               // 0..3  (float4 index along k)

    float acc[4][4];
#pragma unroll
    for (int i = 0; i < 4; i++)
#pragma unroll
        for (int j = 0; j < 4; j++) acc[i][j] = 0.f;

    for (int k0 = 0; k0 < K; k0 += 16) {
        // Load A tile (64 x 16) and B tile (64 x 16), transposed into [kk][row]
        float4 a = *(const float4*)(A + (size_t)(m0 + lr) * K + k0 + lk * 4);
        float4 bvec = *(const float4*)(B + (size_t)(n0 + lr) * K + k0 + lk * 4);
        As[(lk * 4 + 0) * 64 + lr] = a.x;
        As[(lk * 4 + 1) * 64 + lr] = a.y;
        As[(lk * 4 + 2) * 64 + lr] = a.z;
        As[(lk * 4 + 3) * 64 + lr] = a.w;
        Bs[(lk * 4 + 0) * 64 + lr] = bvec.x;
        Bs[(lk * 4 + 1) * 64 + lr] = bvec.y;
        Bs[(lk * 4 + 2) * 64 + lr] = bvec.z;
        Bs[(lk * 4 + 3) * 64 + lr] = bvec.w;
        __syncthreads();

#pragma unroll
        for (int kk = 0; kk < 16; kk++) {
            float4 av = *(const float4*)(As + kk * 64 + ty * 4);
            float4 bv = *(const float4*)(Bs + kk * 64 + tx * 4);
            float ar[4] = {av.x, av.y, av.z, av.w};
            float br[4] = {bv.x, bv.y, bv.z, bv.w};
#pragma unroll
            for (int i = 0; i < 4; i++)
#pragma unroll
                for (int j = 0; j < 4; j++)
                    acc[i][j] = fmaf(ar[i], br[j], acc[i][j]);
        }
        __syncthreads();
    }

#pragma unroll
    for (int i = 0; i < 4; i++) {
        const int m = m0 + ty * 4 + i;
        float* crow = C + (size_t)m * N + n0 + tx * 4;
        float4 out;
        out.x = acc[i][0] + bias[n0 + tx * 4 + 0];
        out.y = acc[i][1] + bias[n0 + tx * 4 + 1];
        out.z = acc[i][2] + bias[n0 + tx * 4 + 2];
        out.w = acc[i][3] + bias[n0 + tx * 4 + 3];
        *(float4*)crow = out;
    }
}

// ---------------------------------------------------------------------------
// Flash attention (non-causal, GQA).
// Grid: (SEQ/BQ, NUM_HEADS, BS). Block: BQ=128 threads, one thread per q row.
// K/V tiles (BK=64 x 64) staged in smem; scores scratch P in padded smem.
// Q row and O accumulator live in registers (16 float4 each).
// ---------------------------------------------------------------------------
#define BQ 128
#define BK 64

__global__ __launch_bounds__(BQ)
void attn_kernel(const float* __restrict__ Q, const float* __restrict__ Kb,
                 const float* __restrict__ Vb, float* __restrict__ O)
{
    extern __shared__ float sm[];
    float* Ks = sm;                    // 64*64 floats
    float* Vs = sm + 64 * 64;          // 64*64 floats
    float* Ps = sm + 2 * 64 * 64;      // BQ * 65 floats (padded)

    const int t  = threadIdx.x;        // q row within tile
    const int h  = blockIdx.y;
    const int b  = blockIdx.z;
    const int g  = h >> 2;             // kv group = h / (NUM_HEADS/N_GROUP)
    const int sq = blockIdx.x * BQ + t;

    // Load q row, pre-scaled by 1/sqrt(d)
    float4 q4[16];
    {
        const float4* qp = (const float4*)(Q + ((size_t)(b * SEQ + sq)) * D_MODEL + h * HEAD_DIM);
        const float scale = 0.125f;    // 1/sqrt(64)
#pragma unroll
        for (int i = 0; i < 16; i++) {
            float4 v = qp[i];
            q4[i] = make_float4(v.x * scale, v.y * scale, v.z * scale, v.w * scale);
        }
    }

    float4 o4[16];
#pragma unroll
    for (int i = 0; i < 16; i++) o4[i] = make_float4(0.f, 0.f, 0.f, 0.f);
    float m = -1e30f, l = 0.f;

    float* myP = Ps + t * 65;

    for (int kt = 0; kt < SEQ / BK; kt++) {
        __syncthreads();   // previous tile's compute finished before overwrite
        // Cooperative load of K and V tiles: 64 rows x 64 floats each
        {
            const float* kbase = Kb + ((size_t)(b * SEQ + kt * BK)) * KV_DIM + g * HEAD_DIM;
            const float* vbase = Vb + ((size_t)(b * SEQ + kt * BK)) * KV_DIM + g * HEAD_DIM;
#pragma unroll
            for (int i = t; i < 64 * 16; i += BQ) {
                int r = i >> 4, c = i & 15;
                ((float4*)Ks)[i] = *(const float4*)(kbase + (size_t)r * KV_DIM + c * 4);
                ((float4*)Vs)[i] = *(const float4*)(vbase + (size_t)r * KV_DIM + c * 4);
            }
        }
        __syncthreads();

        // S = q . K_j  for 64 keys, 4 at a time (register-blocked)
        float mt = m;
        for (int j0 = 0; j0 < BK; j0 += 4) {
            float a0 = 0.f, a1 = 0.f, a2 = 0.f, a3 = 0.f;
            const float4* k0 = (const float4*)(Ks + (j0 + 0) * 64);
            const float4* k1 = (const float4*)(Ks + (j0 + 1) * 64);
            const float4* k2 = (const float4*)(Ks + (j0 + 2) * 64);
            const float4* k3 = (const float4*)(Ks + (j0 + 3) * 64);
#pragma unroll
            for (int d = 0; d < 16; d++) {
                float4 qq = q4[d];
                float4 w0 = k0[d], w1 = k1[d], w2 = k2[d], w3 = k3[d];
                a0 = fmaf(qq.x, w0.x, a0); a0 = fmaf(qq.y, w0.y, a0);
                a0 = fmaf(qq.z, w0.z, a0); a0 = fmaf(qq.w, w0.w, a0);
                a1 = fmaf(qq.x, w1.x, a1); a1 = fmaf(qq.y, w1.y, a1);
                a1 = fmaf(qq.z, w1.z, a1); a1 = fmaf(qq.w, w1.w, a1);
                a2 = fmaf(qq.x, w2.x, a2); a2 = fmaf(qq.y, w2.y, a2);
                a2 = fmaf(qq.z, w2.z, a2); a2 = fmaf(qq.w, w2.w, a2);
                a3 = fmaf(qq.x, w3.x, a3); a3 = fmaf(qq.y, w3.y, a3);
                a3 = fmaf(qq.z, w3.z, a3); a3 = fmaf(qq.w, w3.w, a3);
            }
            myP[j0 + 0] = a0;
            myP[j0 + 1] = a1;
            myP[j0 + 2] = a2;
            myP[j0 + 3] = a3;
            mt = fmaxf(mt, fmaxf(fmaxf(a0, a1), fmaxf(a2, a3)));
        }

        // Online softmax rescale
        float corr = __expf(m - mt);
        l *= corr;
#pragma unroll
        for (int i = 0; i < 16; i++) {
            o4[i].x *= corr; o4[i].y *= corr; o4[i].z *= corr; o4[i].w *= corr;
        }

        // O += P @ V
        for (int j = 0; j < BK; j++) {
            float p = __expf(myP[j] - mt);
            l += p;
            const float4* vv = (const float4*)(Vs + j * 64);
#pragma unroll
            for (int i = 0; i < 16; i++) {
                float4 w = vv[i];
                o4[i].x = fmaf(p, w.x, o4[i].x);
                o4[i].y = fmaf(p, w.y, o4[i].y);
                o4[i].z = fmaf(p, w.z, o4[i].z);
                o4[i].w = fmaf(p, w.w, o4[i].w);
            }
        }
        m = mt;
    }

    const float inv = 1.f / l;
    float4* op = (float4*)(O + ((size_t)(b * SEQ + sq)) * D_MODEL + h * HEAD_DIM);
#pragma unroll
    for (int i = 0; i < 16; i++) {
        op[i] = make_float4(o4[i].x * inv, o4[i].y * inv, o4[i].z * inv, o4[i].w * inv);
    }
}

// ---------------------------------------------------------------------------
// Launch
// ---------------------------------------------------------------------------
extern "C" void kernel_launch(void* const* d_in, const int* in_sizes, int n_in,
                              void* d_out, int out_size)
{
    const float* h    = (const float*)d_in[0];
    const float* wq_w = (const float*)d_in[1];
    const float* wq_b = (const float*)d_in[2];
    const float* wk_w = (const float*)d_in[3];
    const float* wk_b = (const float*)d_in[4];
    const float* wv_w = (const float*)d_in[5];
    const float* wv_b = (const float*)d_in[6];
    float* out = (float*)d_out;

    float* qb; cudaGetSymbolAddress((void**)&qb, g_q);
    float* kb; cudaGetSymbolAddress((void**)&kb, g_k);
    float* vb; cudaGetSymbolAddress((void**)&vb, g_v);

    // QKV projections
    {
        dim3 blk(256);
        dim3 gq(D_MODEL / 64, ROWS / 64);
        gemm_nt_bias<<<gq, blk>>>(h, wq_w, wq_b, qb, ROWS, D_MODEL, D_MODEL);
        dim3 gk(KV_DIM / 64, ROWS / 64);
        gemm_nt_bias<<<gk, blk>>>(h, wk_w, wk_b, kb, ROWS, KV_DIM, D_MODEL);
        gemm_nt_bias<<<gk, blk>>>(h, wv_w, wv_b, vb, ROWS, KV_DIM, D_MODEL);
    }

    // Flash attention
    {
        const size_t smem = (size_t)(2 * 64 * 64 + BQ * 65) * sizeof(float); // 66048 B
        cudaFuncSetAttribute(attn_kernel, cudaFuncAttributeMaxDynamicSharedMemorySize, (int)smem);
        dim3 grid(SEQ / BQ, NUM_HEADS, BS);
        attn_kernel<<<grid, BQ, smem>>>(qb, kb, vb, out);
    }
}

// round 4
// speedup vs baseline: 1.0014x; 1.0007x over previous
#include <cuda_runtime.h>
#include <cuda_bf16.h>
#include <cstddef>

// Problem constants
#define D_MODEL   1024
#define NUM_HEADS 16
#define N_GROUP   4
#define HEAD_DIM  64
#define KV_DIM    (N_GROUP * HEAD_DIM)   // 256
#define BS        2
#define SEQ       2048
#define ROWS      (BS * SEQ)             // 4096

// Scratch buffers (device globals: no allocation allowed in kernel_launch)
__device__ float g_q[ROWS * D_MODEL];   // 16 MB
__device__ float g_k[ROWS * KV_DIM];    //  4 MB
__device__ float g_v[ROWS * KV_DIM];    //  4 MB

// ---------------------------------------------------------------------------
// GEMM: C[m][n] = sum_k A[m][k] * B[n][k] + bias[n]
// A: [M,K] row-major, B: [N,K] row-major (i.e. x @ W^T + b, torch Linear)
// 64x64 tile, 256 threads, 4x4 per thread, k-step 16.
// ---------------------------------------------------------------------------
__global__ __launch_bounds__(256)
void gemm_nt_bias(const float* __restrict__ A, const float* __restrict__ B,
                  const float* __restrict__ bias, float* __restrict__ C,
                  int M, int N, int K)
{
    __shared__ float As[16 * 64];
    __shared__ float Bs[16 * 64];

    const int tid = threadIdx.x;          // 0..255
    const int tx  = tid & 15;             // 0..15
    const int ty  = tid >> 4;             // 0..15
    const int m0  = blockIdx.y * 64;
    const int n0  = blockIdx.x * 64;

    const int lr = tid >> 2;              // 0..63 (row within tile for loading)
    const int lk = tid & 3;               // 0..3  (float4 index along k)

    float acc[4][4];
#pragma unroll
    for (int i = 0; i < 4; i++)
#pragma unroll
        for (int j = 0; j < 4; j++) acc[i][j] = 0.f;

    for (int k0 = 0; k0 < K; k0 += 16) {
        // Load A tile (64 x 16) and B tile (64 x 16), transposed into [kk][row]
        float4 a = *(const float4*)(A + (size_t)(m0 + lr) * K + k0 + lk * 4);
        float4 bvec = *(const float4*)(B + (size_t)(n0 + lr) * K + k0 + lk * 4);
        As[(lk * 4 + 0) * 64 + lr] = a.x;
        As[(lk * 4 + 1) * 64 + lr] = a.y;
        As[(lk * 4 + 2) * 64 + lr] = a.z;
        As[(lk * 4 + 3) * 64 + lr] = a.w;
        Bs[(lk * 4 + 0) * 64 + lr] = bvec.x;
        Bs[(lk * 4 + 1) * 64 + lr] = bvec.y;
        Bs[(lk * 4 + 2) * 64 + lr] = bvec.z;
        Bs[(lk * 4 + 3) * 64 + lr] = bvec.w;
        __syncthreads();

#pragma unroll
        for (int kk = 0; kk < 16; kk++) {
            float4 av = *(const float4*)(As + kk * 64 + ty * 4);
            float4 bv = *(const float4*)(Bs + kk * 64 + tx * 4);
            float ar[4] = {av.x, av.y, av.z, av.w};
            float br[4] = {bv.x, bv.y, bv.z, bv.w};
#pragma unroll
            for (int i = 0; i < 4; i++)
#pragma unroll
                for (int j = 0; j < 4; j++)
                    acc[i][j] = fmaf(ar[i], br[j], acc[i][j]);
        }
        __syncthreads();
    }

#pragma unroll
    for (int i = 0; i < 4; i++) {
        const int m = m0 + ty * 4 + i;
        float* crow = C + (size_t)m * N + n0 + tx * 4;
        float4 out;
        out.x = acc[i][0] + bias[n0 + tx * 4 + 0];
        out.y = acc[i][1] + bias[n0 + tx * 4 + 1];
        out.z = acc[i][2] + bias[n0 + tx * 4 + 2];
        out.w = acc[i][3] + bias[n0 + tx * 4 + 3];
        *(float4*)crow = out;
    }
}

// ---------------------------------------------------------------------------
// Flash attention (non-causal, GQA).
// Grid: (SEQ/BQ, NUM_HEADS, BS). Block: BQ=128 threads, one thread per q row.
// K/V tiles (BK=64 x 64) staged in smem; scores scratch P in padded smem.
// Q row and O accumulator live in registers (16 float4 each).
// ---------------------------------------------------------------------------
#define BQ 128
#define BK 64

__global__ __launch_bounds__(BQ)
void attn_kernel(const float* __restrict__ Q, const float* __restrict__ Kb,
                 const float* __restrict__ Vb, float* __restrict__ O)
{
    extern __shared__ float sm[];
    float* Ks = sm;                    // 64*64 floats
    float* Vs = sm + 64 * 64;          // 64*64 floats
    float* Ps = sm + 2 * 64 * 64;      // BQ * 65 floats (padded)

    const int t  = threadIdx.x;        // q row within tile
    const int h  = blockIdx.y;
    const int b  = blockIdx.z;
    const int g  = h >> 2;             // kv group = h / (NUM_HEADS/N_GROUP)
    const int sq = blockIdx.x * BQ + t;

    // Load q row, pre-scaled by 1/sqrt(d)
    float4 q4[16];
    {
        const float4* qp = (const float4*)(Q + ((size_t)(b * SEQ + sq)) * D_MODEL + h * HEAD_DIM);
        const float scale = 0.125f;    // 1/sqrt(64)
#pragma unroll
        for (int i = 0; i < 16; i++) {
            float4 v = qp[i];
            q4[i] = make_float4(v.x * scale, v.y * scale, v.z * scale, v.w * scale);
        }
    }

    float4 o4[16];
#pragma unroll
    for (int i = 0; i < 16; i++) o4[i] = make_float4(0.f, 0.f, 0.f, 0.f);
    float m = -1e30f, l = 0.f;

    float* myP = Ps + t * 65;

    for (int kt = 0; kt < SEQ / BK; kt++) {
        __syncthreads();   // previous tile's compute finished before overwrite
        // Cooperative load of K and V tiles: 64 rows x 64 floats each
        {
            const float* kbase = Kb + ((size_t)(b * SEQ + kt * BK)) * KV_DIM + g * HEAD_DIM;
            const float* vbase = Vb + ((size_t)(b * SEQ + kt * BK)) * KV_DIM + g * HEAD_DIM;
#pragma unroll
            for (int i = t; i < 64 * 16; i += BQ) {
                int r = i >> 4, c = i & 15;
                ((float4*)Ks)[i] = *(const float4*)(kbase + (size_t)r * KV_DIM + c * 4);
                ((float4*)Vs)[i] = *(const float4*)(vbase + (size_t)r * KV_DIM + c * 4);
            }
        }
        __syncthreads();

        // S = q . K_j  for 64 keys, 4 at a time (register-blocked)
        float mt = m;
        for (int j0 = 0; j0 < BK; j0 += 4) {
            float a0 = 0.f, a1 = 0.f, a2 = 0.f, a3 = 0.f;
            const float4* k0 = (const float4*)(Ks + (j0 + 0) * 64);
            const float4* k1 = (const float4*)(Ks + (j0 + 1) * 64);
            const float4* k2 = (const float4*)(Ks + (j0 + 2) * 64);
            const float4* k3 = (const float4*)(Ks + (j0 + 3) * 64);
#pragma unroll
            for (int d = 0; d < 16; d++) {
                float4 qq = q4[d];
                float4 w0 = k0[d], w1 = k1[d], w2 = k2[d], w3 = k3[d];
                a0 = fmaf(qq.x, w0.x, a0); a0 = fmaf(qq.y, w0.y, a0);
                a0 = fmaf(qq.z, w0.z, a0); a0 = fmaf(qq.w, w0.w, a0);
                a1 = fmaf(qq.x, w1.x, a1); a1 = fmaf(qq.y, w1.y, a1);
                a1 = fmaf(qq.z, w1.z, a1); a1 = fmaf(qq.w, w1.w, a1);
                a2 = fmaf(qq.x, w2.x, a2); a2 = fmaf(qq.y, w2.y, a2);
                a2 = fmaf(qq.z, w2.z, a2); a2 = fmaf(qq.w, w2.w, a2);
                a3 = fmaf(qq.x, w3.x, a3); a3 = fmaf(qq.y, w3.y, a3);
                a3 = fmaf(qq.z, w3.z, a3); a3 = fmaf(qq.w, w3.w, a3);
            }
            myP[j0 + 0] = a0;
            myP[j0 + 1] = a1;
            myP[j0 + 2] = a2;
            myP[j0 + 3] = a3;
            mt = fmaxf(mt, fmaxf(fmaxf(a0, a1), fmaxf(a2, a3)));
        }

        // Online softmax rescale
        float corr = __expf(m - mt);
        l *= corr;
#pragma unroll
        for (int i = 0; i < 16; i++) {
            o4[i].x *= corr; o4[i].y *= corr; o4[i].z *= corr; o4[i].w *= corr;
        }

        // O += P @ V
        for (int j = 0; j < BK; j++) {
            float p = __expf(myP[j] - mt);
            l += p;
            const float4* vv = (const float4*)(Vs + j * 64);
#pragma unroll
            for (int i = 0; i < 16; i++) {
                float4 w = vv[i];
                o4[i].x = fmaf(p, w.x, o4[i].x);
                o4[i].y = fmaf(p, w.y, o4[i].y);
                o4[i].z = fmaf(p, w.z, o4[i].z);
                o4[i].w = fmaf(p, w.w, o4[i].w);
            }
        }
        m = mt;
    }

    const float inv = 1.f / l;
    float4* op = (float4*)(O + ((size_t)(b * SEQ + sq)) * D_MODEL + h * HEAD_DIM);
#pragma unroll
    for (int i = 0; i < 16; i++) {
        op[i] = make_float4(o4[i].x * inv, o4[i].y * inv, o4[i].z * inv, o4[i].w * inv);
    }
}

// ---------------------------------------------------------------------------
// Launch
// ---------------------------------------------------------------------------
extern "C" void kernel_launch(void* const* d_in, const int* in_sizes, int n_in,
                              void* d_out, int out_size)
{
    const float* h    = (const float*)d_in[0];
    const float* wq_w = (const float*)d_in[1];
    const float* wq_b = (const float*)d_in[2];
    const float* wk_w = (const float*)d_in[3];
    const float* wk_b = (const float*)d_in[4];
    const float* wv_w = (const float*)d_in[5];
    const float* wv_b = (const float*)d_in[6];
    float* out = (float*)d_out;

    float* qb; cudaGetSymbolAddress((void**)&qb, g_q);
    float* kb; cudaGetSymbolAddress((void**)&kb, g_k);
    float* vb; cudaGetSymbolAddress((void**)&vb, g_v);

    // QKV projections
    {
        dim3 blk(256);
        dim3 gq(D_MODEL / 64, ROWS / 64);
        gemm_nt_bias<<<gq, blk>>>(h, wq_w, wq_b, qb, ROWS, D_MODEL, D_MODEL);
        dim3 gk(KV_DIM / 64, ROWS / 64);
        gemm_nt_bias<<<gk, blk>>>(h, wk_w, wk_b, kb, ROWS, KV_DIM, D_MODEL);
        gemm_nt_bias<<<gk, blk>>>(h, wv_w, wv_b, vb, ROWS, KV_DIM, D_MODEL);
    }

    // Flash attention
    {
        const size_t smem = (size_t)(2 * 64 * 64 + BQ * 65) * sizeof(float); // 66048 B
        cudaFuncSetAttribute(attn_kernel, cudaFuncAttributeMaxDynamicSharedMemorySize, (int)smem);
        dim3 grid(SEQ / BQ, NUM_HEADS, BS);
        attn_kernel<<<grid, BQ, smem>>>(qb, kb, vb, out);
    }
}

// round 6
// speedup vs baseline: 1.0021x; 1.0007x over previous
#include <cuda_runtime.h>
#include <cuda_bf16.h>
#include <cstddef>

// Problem constants
#define D_MODEL   1024
#define NUM_HEADS 16
#define N_GROUP   4
#define HEAD_DIM  64
#define KV_DIM    (N_GROUP * HEAD_DIM)   // 256
#define BS        2
#define SEQ       2048
#define ROWS      (BS * SEQ)             // 4096

// Scratch buffers (device globals: no allocation allowed in kernel_launch)
__device__ float g_q[ROWS * D_MODEL];   // 16 MB
__device__ float g_k[ROWS * KV_DIM];    //  4 MB
__device__ float g_v[ROWS * KV_DIM];    //  4 MB

// ---------------------------------------------------------------------------
// GEMM: C[m][n] = sum_k A[m][k] * B[n][k] + bias[n]
// A: [M,K] row-major, B: [N,K] row-major (i.e. x @ W^T + b, torch Linear)
// 64x64 tile, 256 threads, 4x4 per thread, k-step 16.
// ---------------------------------------------------------------------------
__global__ __launch_bounds__(256)
void gemm_nt_bias(const float* __restrict__ A, const float* __restrict__ B,
                  const float* __restrict__ bias, float* __restrict__ C,
                  int M, int N, int K)
{
    __shared__ float As[16 * 64];
    __shared__ float Bs[16 * 64];

    const int tid = threadIdx.x;          // 0..255
    const int tx  = tid & 15;             // 0..15
    const int ty  = tid >> 4;             // 0..15
    const int m0  = blockIdx.y * 64;
    const int n0  = blockIdx.x * 64;

    const int lr = tid >> 2;              // 0..63 (row within tile for loading)
    const int lk = tid & 3;               // 0..3  (float4 index along k)

    float acc[4][4];
#pragma unroll
    for (int i = 0; i < 4; i++)
#pragma unroll
        for (int j = 0; j < 4; j++) acc[i][j] = 0.f;

    for (int k0 = 0; k0 < K; k0 += 16) {
        // Load A tile (64 x 16) and B tile (64 x 16), transposed into [kk][row]
        float4 a = *(const float4*)(A + (size_t)(m0 + lr) * K + k0 + lk * 4);
        float4 bvec = *(const float4*)(B + (size_t)(n0 + lr) * K + k0 + lk * 4);
        As[(lk * 4 + 0) * 64 + lr] = a.x;
        As[(lk * 4 + 1) * 64 + lr] = a.y;
        As[(lk * 4 + 2) * 64 + lr] = a.z;
        As[(lk * 4 + 3) * 64 + lr] = a.w;
        Bs[(lk * 4 + 0) * 64 + lr] = bvec.x;
        Bs[(lk * 4 + 1) * 64 + lr] = bvec.y;
        Bs[(lk * 4 + 2) * 64 + lr] = bvec.z;
        Bs[(lk * 4 + 3) * 64 + lr] = bvec.w;
        __syncthreads();

#pragma unroll
        for (int kk = 0; kk < 16; kk++) {
            float4 av = *(const float4*)(As + kk * 64 + ty * 4);
            float4 bv = *(const float4*)(Bs + kk * 64 + tx * 4);
            float ar[4] = {av.x, av.y, av.z, av.w};
            float br[4] = {bv.x, bv.y, bv.z, bv.w};
#pragma unroll
            for (int i = 0; i < 4; i++)
#pragma unroll
                for (int j = 0; j < 4; j++)
                    acc[i][j] = fmaf(ar[i], br[j], acc[i][j]);
        }
        __syncthreads();
    }

#pragma unroll
    for (int i = 0; i < 4; i++) {
        const int m = m0 + ty * 4 + i;
        float* crow = C + (size_t)m * N + n0 + tx * 4;
        float4 out;
        out.x = acc[i][0] + bias[n0 + tx * 4 + 0];
        out.y = acc[i][1] + bias[n0 + tx * 4 + 1];
        out.z = acc[i][2] + bias[n0 + tx * 4 + 2];
        out.w = acc[i][3] + bias[n0 + tx * 4 + 3];
        *(float4*)crow = out;
    }
}

// ---------------------------------------------------------------------------
// Flash attention (non-causal, GQA).
// Grid: (SEQ/BQ, NUM_HEADS, BS). Block: BQ=128 threads, one thread per q row.
// K/V tiles (BK=64 x 64) staged in smem; scores scratch P in padded smem.
// Q row and O accumulator live in registers (16 float4 each).
// ---------------------------------------------------------------------------
#define BQ 128
#define BK 64

__global__ __launch_bounds__(BQ)
void attn_kernel(const float* __restrict__ Q, const float* __restrict__ Kb,
                 const float* __restrict__ Vb, float* __restrict__ O)
{
    extern __shared__ float sm[];
    float* Ks = sm;                    // 64*64 floats
    float* Vs = sm + 64 * 64;          // 64*64 floats
    float* Ps = sm + 2 * 64 * 64;      // BQ * 65 floats (padded)

    const int t  = threadIdx.x;        // q row within tile
    const int h  = blockIdx.y;
    const int b  = blockIdx.z;
    const int g  = h >> 2;             // kv group = h / (NUM_HEADS/N_GROUP)
    const int sq = blockIdx.x * BQ + t;

    // Load q row, pre-scaled by 1/sqrt(d)
    float4 q4[16];
    {
        const float4* qp = (const float4*)(Q + ((size_t)(b * SEQ + sq)) * D_MODEL + h * HEAD_DIM);
        const float scale = 0.125f;    // 1/sqrt(64)
#pragma unroll
        for (int i = 0; i < 16; i++) {
            float4 v = qp[i];
            q4[i] = make_float4(v.x * scale, v.y * scale, v.z * scale, v.w * scale);
        }
    }

    float4 o4[16];
#pragma unroll
    for (int i = 0; i < 16; i++) o4[i] = make_float4(0.f, 0.f, 0.f, 0.f);
    float m = -1e30f, l = 0.f;

    float* myP = Ps + t * 65;

    for (int kt = 0; kt < SEQ / BK; kt++) {
        __syncthreads();   // previous tile's compute finished before overwrite
        // Cooperative load of K and V tiles: 64 rows x 64 floats each
        {
            const float* kbase = Kb + ((size_t)(b * SEQ + kt * BK)) * KV_DIM + g * HEAD_DIM;
            const float* vbase = Vb + ((size_t)(b * SEQ + kt * BK)) * KV_DIM + g * HEAD_DIM;
#pragma unroll
            for (int i = t; i < 64 * 16; i += BQ) {
                int r = i >> 4, c = i & 15;
                ((float4*)Ks)[i] = *(const float4*)(kbase + (size_t)r * KV_DIM + c * 4);
                ((float4*)Vs)[i] = *(const float4*)(vbase + (size_t)r * KV_DIM + c * 4);
            }
        }
        __syncthreads();

        // S = q . K_j  for 64 keys, 4 at a time (register-blocked)
        float mt = m;
        for (int j0 = 0; j0 < BK; j0 += 4) {
            float a0 = 0.f, a1 = 0.f, a2 = 0.f, a3 = 0.f;
            const float4* k0 = (const float4*)(Ks + (j0 + 0) * 64);
            const float4* k1 = (const float4*)(Ks + (j0 + 1) * 64);
            const float4* k2 = (const float4*)(Ks + (j0 + 2) * 64);
            const float4* k3 = (const float4*)(Ks + (j0 + 3) * 64);
#pragma unroll
            for (int d = 0; d < 16; d++) {
                float4 qq = q4[d];
                float4 w0 = k0[d], w1 = k1[d], w2 = k2[d], w3 = k3[d];
                a0 = fmaf(qq.x, w0.x, a0); a0 = fmaf(qq.y, w0.y, a0);
                a0 = fmaf(qq.z, w0.z, a0); a0 = fmaf(qq.w, w0.w, a0);
                a1 = fmaf(qq.x, w1.x, a1); a1 = fmaf(qq.y, w1.y, a1);
                a1 = fmaf(qq.z, w1.z, a1); a1 = fmaf(qq.w, w1.w, a1);
                a2 = fmaf(qq.x, w2.x, a2); a2 = fmaf(qq.y, w2.y, a2);
                a2 = fmaf(qq.z, w2.z, a2); a2 = fmaf(qq.w, w2.w, a2);
                a3 = fmaf(qq.x, w3.x, a3); a3 = fmaf(qq.y, w3.y, a3);
                a3 = fmaf(qq.z, w3.z, a3); a3 = fmaf(qq.w, w3.w, a3);
            }
            myP[j0 + 0] = a0;
            myP[j0 + 1] = a1;
            myP[j0 + 2] = a2;
            myP[j0 + 3] = a3;
            mt = fmaxf(mt, fmaxf(fmaxf(a0, a1), fmaxf(a2, a3)));
        }

        // Online softmax rescale
        float corr = __expf(m - mt);
        l *= corr;
#pragma unroll
        for (int i = 0; i < 16; i++) {
            o4[i].x *= corr; o4[i].y *= corr; o4[i].z *= corr; o4[i].w *= corr;
        }

        // O += P @ V
        for (int j = 0; j < BK; j++) {
            float p = __expf(myP[j] - mt);
            l += p;
            const float4* vv = (const float4*)(Vs + j * 64);
#pragma unroll
            for (int i = 0; i < 16; i++) {
                float4 w = vv[i];
                o4[i].x = fmaf(p, w.x, o4[i].x);
                o4[i].y = fmaf(p, w.y, o4[i].y);
                o4[i].z = fmaf(p, w.z, o4[i].z);
                o4[i].w = fmaf(p, w.w, o4[i].w);
            }
        }
        m = mt;
    }

    const float inv = 1.f / l;
    float4* op = (float4*)(O + ((size_t)(b * SEQ + sq)) * D_MODEL + h * HEAD_DIM);
#pragma unroll
    for (int i = 0; i < 16; i++) {
        op[i] = make_float4(o4[i].x * inv, o4[i].y * inv, o4[i].z * inv, o4[i].w * inv);
    }
}

// ---------------------------------------------------------------------------
// Launch
// ---------------------------------------------------------------------------
extern "C" void kernel_launch(void* const* d_in, const int* in_sizes, int n_in,
                              void* d_out, int out_size)
{
    const float* h    = (const float*)d_in[0];
    const float* wq_w = (const float*)d_in[1];
    const float* wq_b = (const float*)d_in[2];
    const float* wk_w = (const float*)d_in[3];
    const float* wk_b = (const float*)d_in[4];
    const float* wv_w = (const float*)d_in[5];
    const float* wv_b = (const float*)d_in[6];
    float* out = (float*)d_out;

    float* qb; cudaGetSymbolAddress((void**)&qb, g_q);
    float* kb; cudaGetSymbolAddress((void**)&kb, g_k);
    float* vb; cudaGetSymbolAddress((void**)&vb, g_v);

    // QKV projections
    {
        dim3 blk(256);
        dim3 gq(D_MODEL / 64, ROWS / 64);
        gemm_nt_bias<<<gq, blk>>>(h, wq_w, wq_b, qb, ROWS, D_MODEL, D_MODEL);
        dim3 gk(KV_DIM / 64, ROWS / 64);
        gemm_nt_bias<<<gk, blk>>>(h, wk_w, wk_b, kb, ROWS, KV_DIM, D_MODEL);
        gemm_nt_bias<<<gk, blk>>>(h, wv_w, wv_b, vb, ROWS, KV_DIM, D_MODEL);
    }

    // Flash attention
    {
        const size_t smem = (size_t)(2 * 64 * 64 + BQ * 65) * sizeof(float); // 66048 B
        cudaFuncSetAttribute(attn_kernel, cudaFuncAttributeMaxDynamicSharedMemorySize, (int)smem);
        dim3 grid(SEQ / BQ, NUM_HEADS, BS);
        attn_kernel<<<grid, BQ, smem>>>(qb, kb, vb, out);
    }
}